// round 4
// baseline (speedup 1.0000x reference)
#include <cuda_runtime.h>
#include <math.h>

#define B_    2048
#define T_    128
#define D_    20
#define H_    128
#define STEPS 127          // T-1
#define KE    148          // H + D extended contraction
#define RPB   16           // batch rows per block (2048 = 16 * 128)
#define NBLK  128
#define HPAD  20           // row stride of k-major hx (80B: 16B-aligned LDS.128)
#define NTHR  512

typedef unsigned long long u64;

// Scratch (allocation-free: __device__ globals)
__device__ float4 g_wpack[KE * H_];   // [k][u] = {W_i, W_f, W_g, W_o}
__device__ float4 g_bias4[H_];        // combined b_ih + b_hh per unit
__device__ float  g_alpha[B_ * D_];   // softmax(xw) per batch row

// ---------------------------------------------------------------------------
__device__ __forceinline__ u64 ffma2(u64 a, u64 b, u64 c) {
    u64 d;
    asm("fma.rn.f32x2 %0, %1, %2, %3;" : "=l"(d) : "l"(a), "l"(b), "l"(c));
    return d;
}
__device__ __forceinline__ u64 dup2(float x) {
    u64 d;
    asm("mov.b64 %0, {%1, %1};" : "=l"(d) : "f"(x));
    return d;
}
__device__ __forceinline__ float sigf(float x) {
    return __frcp_rn(1.f + __expf(-x));
}
__device__ __forceinline__ float tanhfast(float x) {
    // tanh(x) = 1 - 2/(exp(2x)+1); saturates correctly at +/-inf
    return fmaf(-2.f, __frcp_rn(__expf(2.f * x) + 1.f), 1.f);
}

// ---------------------------------------------------------------------------
// K0: pack weights k-major as float4 per (k, unit); combine biases.
// ---------------------------------------------------------------------------
__global__ void pack_kernel(const float* __restrict__ W_ih,
                            const float* __restrict__ W_hh,
                            const float* __restrict__ b_ih,
                            const float* __restrict__ b_hh) {
    int u = threadIdx.x;       // 0..127
    int k = blockIdx.x;        // 0..147
    float4 w;
    if (k < H_) {
        w.x = W_hh[(u)       * H_ + k];
        w.y = W_hh[(128 + u) * H_ + k];
        w.z = W_hh[(256 + u) * H_ + k];
        w.w = W_hh[(384 + u) * H_ + k];
    } else {
        int d = k - H_;
        w.x = W_ih[(u)       * D_ + d];
        w.y = W_ih[(128 + u) * D_ + d];
        w.z = W_ih[(256 + u) * D_ + d];
        w.w = W_ih[(384 + u) * D_ + d];
    }
    g_wpack[k * H_ + u] = w;
    if (k == 0) {
        g_bias4[u] = make_float4(b_ih[u]       + b_hh[u],
                                 b_ih[128 + u] + b_hh[128 + u],
                                 b_ih[256 + u] + b_hh[256 + u],
                                 b_ih[384 + u] + b_hh[384 + u]);
    }
}

// ---------------------------------------------------------------------------
// K1: alpha = softmax_d(sum_t X[b,t,d] * w_x[t]) (hs per-row scalar cancels).
// Also writes the entire X_tilde output. One warp per batch row.
// ---------------------------------------------------------------------------
__global__ void __launch_bounds__(256, 1)
attn_kernel(const float* __restrict__ X,
            const float* __restrict__ W_attn,
            float* __restrict__ out_xt) {
    __shared__ float wx_s[T_];
    int tid = threadIdx.x;
    for (int i = tid; i < T_; i += 256) wx_s[i] = W_attn[2 * H_ + i];
    __syncthreads();

    int b    = (blockIdx.x * 256 + tid) >> 5;
    int lane = tid & 31;
    if (b >= B_) return;

    const float* xb = X + (long)b * T_ * D_;
    float acc = 0.f;
    if (lane < D_) {
        #pragma unroll 4
        for (int t = 0; t < T_; t++) acc = fmaf(xb[t * D_ + lane], wx_s[t], acc);
    }
    float v = (lane < D_) ? acc : -INFINITY;
    #pragma unroll
    for (int off = 16; off; off >>= 1) v = fmaxf(v, __shfl_xor_sync(0xffffffffu, v, off));
    float e = (lane < D_) ? __expf(acc - v) : 0.f;
    float s = e;
    #pragma unroll
    for (int off = 16; off; off >>= 1) s += __shfl_xor_sync(0xffffffffu, s, off);
    float alpha = e / s;

    if (lane < D_) {
        g_alpha[b * D_ + lane] = alpha;
        for (int t = 0; t < STEPS; t++)
            out_xt[((long)b * STEPS + t) * D_ + lane] = alpha * xb[t * D_ + lane];
    }
}

// ---------------------------------------------------------------------------
// K2: persistent LSTM, 512 threads (4 warps/SMSP for latency hiding).
// Block owns 16 batch rows. Thread (u = tid&127, q = tid>>7) computes all
// 4 gates of unit u for 4 rows (q*4..q*4+3) = 2 f32x2 row-pairs.
// hx is k-major in SMEM; each thread's h-load is one 16B-aligned LDS.128
// (all lanes of a warp same address -> broadcast, conflict-free).
// Weight stream: 2-iteration-deep register ring (8 k lookahead) to cover
// L2 latency (weights don't fit L1).
// ---------------------------------------------------------------------------
__global__ void __launch_bounds__(NTHR, 1)
lstm_main(const float* __restrict__ X, float* __restrict__ out_enc) {
    __shared__ __align__(16) float hxT[KE * HPAD];  // [k][row]

    int tid = threadIdx.x;
    int u   = tid & 127;
    int q   = tid >> 7;               // 0..3 -> rows q*4 .. q*4+3
    int row0 = blockIdx.x * RPB;

    for (int i = tid; i < KE * HPAD; i += NTHR) hxT[i] = 0.f;

    // x_tilde staging: one slot per thread (320 slots < 512 threads)
    bool sok = tid < RPB * D_;
    int  sr = tid / D_, sd = tid % D_;
    const float* xp = sok ? X + ((long)(row0 + sr) * T_) * D_ + sd : X;
    float al = sok ? g_alpha[(row0 + sr) * D_ + sd] : 0.f;
    float* stslot = &hxT[(H_ + sd) * HPAD + sr];

    // stage x_tilde for t = 0
    if (sok) *stslot = al * xp[0];

    float4 b4 = g_bias4[u];
    u64 bias2[4] = { dup2(b4.x), dup2(b4.y), dup2(b4.z), dup2(b4.w) };

    float c[4];
    #pragma unroll
    for (int r = 0; r < 4; r++) c[r] = 0.f;

    const float4* __restrict__ wp = g_wpack + u;
    const float* hbase = hxT + q * 4;          // this thread's 4-row slice
    float* hwr = &hxT[u * HPAD + q * 4];       // where this thread writes h

    // out base: rows row0+q*4 .., unit u
    float* ob = out_enc + ((long)(row0 + q * 4) * STEPS) * H_ + u;
    const long rowstride = (long)STEPS * H_;

    __syncthreads();

    for (int t = 0; t < STEPS; t++) {
        // prefetch next step's X early (registers), consumed after sync1
        float xnext = 0.f;
        if (sok && t + 1 < STEPS) xnext = __ldg(&xp[(t + 1) * D_]);

        u64 acc0[4], acc1[4];                  // [gate] for row-pair 0 / 1
        #pragma unroll
        for (int g = 0; g < 4; g++) { acc0[g] = bias2[g]; acc1[g] = bias2[g]; }

        // 2-deep ring of 4-k groups: loads issued 8 k (~2 iters) ahead
        float4 wr0[4], wr1[4];
        #pragma unroll
        for (int j = 0; j < 4; j++) wr0[j] = __ldg(&wp[(0 + j) * H_]);
        #pragma unroll
        for (int j = 0; j < 4; j++) wr1[j] = __ldg(&wp[(4 + j) * H_]);

        #pragma unroll 1
        for (int kb = 0; kb < KE; kb += 4) {
            bool odd = (kb >> 2) & 1;
            #pragma unroll
            for (int j = 0; j < 4; j++) {
                float4 w = odd ? wr1[j] : wr0[j];
                const ulonglong2 hv = *(const ulonglong2*)(hbase + (kb + j) * HPAD);
                u64 dx = dup2(w.x), dy = dup2(w.y), dz = dup2(w.z), dw = dup2(w.w);
                acc0[0] = ffma2(dx, hv.x, acc0[0]);
                acc0[1] = ffma2(dy, hv.x, acc0[1]);
                acc0[2] = ffma2(dz, hv.x, acc0[2]);
                acc0[3] = ffma2(dw, hv.x, acc0[3]);
                acc1[0] = ffma2(dx, hv.y, acc1[0]);
                acc1[1] = ffma2(dy, hv.y, acc1[1]);
                acc1[2] = ffma2(dz, hv.y, acc1[2]);
                acc1[3] = ffma2(dw, hv.y, acc1[3]);
            }
            if (kb + 8 < KE) {
                if (odd) {
                    #pragma unroll
                    for (int j = 0; j < 4; j++) wr1[j] = __ldg(&wp[(kb + 8 + j) * H_]);
                } else {
                    #pragma unroll
                    for (int j = 0; j < 4; j++) wr0[j] = __ldg(&wp[(kb + 8 + j) * H_]);
                }
            }
        }
        __syncthreads();   // all GEMM reads of hxT done before it is rewritten

        // stage x_tilde for t+1 (independent of h -> do before activations)
        if (sok && t + 1 < STEPS) *stslot = al * xnext;

        // epilogue: 2 row-pairs -> 4 rows
        float hn4[4];
        #pragma unroll
        for (int p = 0; p < 2; p++) {
            u64 ai = p ? acc1[0] : acc0[0];
            u64 af = p ? acc1[1] : acc0[1];
            u64 ag = p ? acc1[2] : acc0[2];
            u64 ao = p ? acc1[3] : acc0[3];
            float2 fi = *(float2*)&ai;
            float2 ff = *(float2*)&af;
            float2 fg = *(float2*)&ag;
            float2 fo = *(float2*)&ao;
            #pragma unroll
            for (int j = 0; j < 2; j++) {
                int r = 2 * p + j;
                float iv = sigf(j ? fi.y : fi.x);
                float fv = sigf(j ? ff.y : ff.x);
                float gv = tanhfast(j ? fg.y : fg.x);
                float ov = sigf(j ? fo.y : fo.x);
                float cn = fmaf(fv, c[r], iv * gv);
                c[r] = cn;
                hn4[r] = ov * tanhfast(cn);
            }
        }
        // h write: one STS.128 per thread
        *(float4*)hwr = make_float4(hn4[0], hn4[1], hn4[2], hn4[3]);
        #pragma unroll
        for (int r = 0; r < 4; r++)
            ob[r * rowstride + (long)t * H_] = hn4[r];

        __syncthreads();   // h + x_tilde visible before next GEMM
    }
}

// ---------------------------------------------------------------------------
extern "C" void kernel_launch(void* const* d_in, const int* in_sizes, int n_in,
                              void* d_out, int out_size) {
    const float* X      = (const float*)d_in[0];
    const float* W_attn = (const float*)d_in[1];
    // d_in[2] = b_attn: cancels in softmax, unused
    const float* W_ih   = (const float*)d_in[3];
    const float* W_hh   = (const float*)d_in[4];
    const float* b_ih   = (const float*)d_in[5];
    const float* b_hh   = (const float*)d_in[6];

    float* out     = (float*)d_out;
    float* out_xt  = out;                              // [B,127,20]
    float* out_enc = out + (long)B_ * STEPS * D_;      // [B,127,128]

    pack_kernel<<<KE, H_>>>(W_ih, W_hh, b_ih, b_hh);
    attn_kernel<<<(B_ * 32) / 256, 256>>>(X, W_attn, out_xt);
    lstm_main<<<NBLK, NTHR>>>(X, out_enc);
}